// round 6
// baseline (speedup 1.0000x reference)
#include <cuda_runtime.h>

#define W_IN    56
#define H_IN    56
#define C_IN    128
#define O_OUT   32
#define N_B     128
#define ROWS    4
#define XPAD    60
#define WTILES  7
#define OTILES  8
#define GTHREADS 224                       // threads per C-half
#define THREADS (2 * GTHREADS)             // 448 = 14 warps

#define XS_FLOATS (ROWS * C_IN * XPAD)     // 30720 floats = 120 KB
#define WS_FLOATS (C_IN * 96)              // 12288 floats = 48 KB
#define SMEM_BYTES ((XS_FLOATS + WS_FLOATS) * 4)   // 172032 B

#define PS_STRIDE 17                        // u64 stride per thread (conflict pad)

typedef unsigned long long u64;

__device__ __forceinline__ u64 ffma2(u64 a, u64 b, u64 c) {
    u64 d;
    asm("fma.rn.f32x2 %0, %1, %2, %3;" : "=l"(d) : "l"(a), "l"(b), "l"(c));
    return d;
}
__device__ __forceinline__ u64 fadd2(u64 a, u64 b) {
    u64 d;
    asm("add.rn.f32x2 %0, %1, %2;" : "=l"(d) : "l"(a), "l"(b));
    return d;
}
__device__ __forceinline__ u64 pack2(float lo, float hi) {
    u64 d;
    asm("mov.b64 %0, {%1, %2};" : "=l"(d) : "f"(lo), "f"(hi));
    return d;
}
__device__ __forceinline__ void unpack2(float& lo, float& hi, u64 v) {
    asm("mov.b64 {%0, %1}, %2;" : "=f"(lo), "=f"(hi) : "l"(v));
}

__global__ __launch_bounds__(THREADS, 1)
void conv1x3_roll_kernel(const float* __restrict__ x,
                         const float* __restrict__ wgt,
                         float* __restrict__ out) {
    extern __shared__ float smem[];
    float* xs = smem;                    // [ROWS][C_IN][XPAD], xs[..][k] = x[w=k-1], halo zeros
    float* ws = smem + XS_FLOATS;        // [C_IN][3][32]: ws[c*96 + kw*32 + o]

    const int tid = threadIdx.x;
    const int n   = blockIdx.y;
    const int h0  = blockIdx.x * ROWS;

    // ---- load weights: wgt[o][c][kw] -> ws[c][kw][o] ----
    for (int i = tid; i < O_OUT * C_IN * 3; i += THREADS) {
        int o   = i / (C_IN * 3);
        int rem = i - o * (C_IN * 3);
        int c   = rem / 3;
        int kw  = rem - c * 3;
        ws[c * 96 + kw * 32 + o] = wgt[i];
    }

    // ---- load 4 x-rows (roll folded in) into padded smem ----
    #pragma unroll
    for (int r = 0; r < ROWS; ++r) {
        int h    = h0 + r;
        int hsrc = (h + H_IN - 1) % H_IN;          // roll(+1, axis=H)
        const float* xbase = x + ((size_t)(n * C_IN) * H_IN + hsrc) * W_IN;
        for (int i = tid; i < C_IN * (W_IN / 4); i += THREADS) {
            int c = i / 14;
            int v = i - c * 14;
            float4 val = *(const float4*)(xbase + (size_t)c * H_IN * W_IN + v * 4);
            float* dst = xs + (r * C_IN + c) * XPAD + 1 + v * 4;
            dst[0] = val.x; dst[1] = val.y; dst[2] = val.z; dst[3] = val.w;
        }
        for (int c = tid; c < C_IN; c += THREADS) {
            float* row = xs + (r * C_IN + c) * XPAD;
            row[0] = 0.0f; row[57] = 0.0f; row[58] = 0.0f; row[59] = 0.0f;
        }
    }
    __syncthreads();

    // ---- per-thread tile: 4 o x 8 w, packed over o-pairs; C split across 2 groups ----
    const int chalf = tid / GTHREADS;          // 0 or 1
    const int t0    = tid - chalf * GTHREADS;  // 0..223
    const int wt = t0 % WTILES;
    const int ot = (t0 / WTILES) % OTILES;
    const int r  = t0 / (WTILES * OTILES);
    const int w0 = wt * 8;
    const int o0 = ot * 4;

    u64 acc[2][8];
    #pragma unroll
    for (int p = 0; p < 2; ++p)
        #pragma unroll
        for (int j = 0; j < 8; ++j) acc[p][j] = 0ULL;

    const float* xp = xs + (size_t)r * C_IN * XPAD + w0;
    const u64*   wq = (const u64*)ws;
    const int cbeg = chalf * (C_IN / 2);

    #pragma unroll 4
    for (int ci = 0; ci < C_IN / 2; ++ci) {
        const int c = cbeg + ci;
        const float* xr = xp + c * XPAD;        // xr[j] = x[w = w0 + j - 1]
        float4 a = *(const float4*)(xr);
        float4 b = *(const float4*)(xr + 4);
        float2 e = *(const float2*)(xr + 8);

        u64 xb[10];
        xb[0] = pack2(a.x, a.x); xb[1] = pack2(a.y, a.y);
        xb[2] = pack2(a.z, a.z); xb[3] = pack2(a.w, a.w);
        xb[4] = pack2(b.x, b.x); xb[5] = pack2(b.y, b.y);
        xb[6] = pack2(b.z, b.z); xb[7] = pack2(b.w, b.w);
        xb[8] = pack2(e.x, e.x); xb[9] = pack2(e.y, e.y);

        const u64* wc = wq + c * 48 + ot * 2;   // c*96 floats = 48 pairs
        u64 wk[3][2];
        #pragma unroll
        for (int kw = 0; kw < 3; ++kw) {
            wk[kw][0] = wc[kw * 16];
            wk[kw][1] = wc[kw * 16 + 1];
        }

        #pragma unroll
        for (int kw = 0; kw < 3; ++kw) {
            #pragma unroll
            for (int j = 0; j < 8; ++j) {
                acc[0][j] = ffma2(wk[kw][0], xb[j + kw], acc[0][j]);
                acc[1][j] = ffma2(wk[kw][1], xb[j + kw], acc[1][j]);
            }
        }
    }

    // ---- cross-group reduction via smem (reuse xs region) ----
    __syncthreads();
    u64* ps = (u64*)smem;                      // 224 * 17 u64 = 30464 B < xs
    if (chalf == 1) {
        u64* dst = ps + (size_t)t0 * PS_STRIDE;
        #pragma unroll
        for (int p = 0; p < 2; ++p)
            #pragma unroll
            for (int j = 0; j < 8; ++j) dst[p * 8 + j] = acc[p][j];
    }
    __syncthreads();

    if (chalf == 0) {
        const u64* src = ps + (size_t)t0 * PS_STRIDE;
        #pragma unroll
        for (int p = 0; p < 2; ++p)
            #pragma unroll
            for (int j = 0; j < 8; ++j)
                acc[p][j] = fadd2(acc[p][j], src[p * 8 + j]);

        const int h = h0 + r;
        float res[4][8];
        #pragma unroll
        for (int p = 0; p < 2; ++p)
            #pragma unroll
            for (int j = 0; j < 8; ++j) {
                float lo, hi;
                unpack2(lo, hi, acc[p][j]);
                res[2 * p][j]     = lo;
                res[2 * p + 1][j] = hi;
            }

        #pragma unroll
        for (int oo = 0; oo < 4; ++oo) {
            float* op = out + (((size_t)n * O_OUT + (o0 + oo)) * H_IN + h) * W_IN + w0;
            *(float4*)(op)     = make_float4(res[oo][0], res[oo][1], res[oo][2], res[oo][3]);
            *(float4*)(op + 4) = make_float4(res[oo][4], res[oo][5], res[oo][6], res[oo][7]);
        }
    }
}

extern "C" void kernel_launch(void* const* d_in, const int* in_sizes, int n_in,
                              void* d_out, int out_size) {
    const float* x = (const float*)d_in[0];
    const float* w = (const float*)d_in[1];
    float* out = (float*)d_out;

    cudaFuncSetAttribute(conv1x3_roll_kernel,
                         cudaFuncAttributeMaxDynamicSharedMemorySize, SMEM_BYTES);

    dim3 grid(H_IN / ROWS, N_B);   // (14, 128)
    conv1x3_roll_kernel<<<grid, THREADS, SMEM_BYTES>>>(x, w, out);
}

// round 9
// speedup vs baseline: 1.0011x; 1.0011x over previous
#include <cuda_runtime.h>

#define W_IN    56
#define H_IN    56
#define C_IN    128
#define O_OUT   32
#define N_B     128
#define ROWS    4
#define XPAD    60
#define WTILES  7
#define OTILES  8
#define GTHREADS 224                       // threads per C-half
#define THREADS (2 * GTHREADS)             // 448 = 14 warps

#define XS_FLOATS (ROWS * C_IN * XPAD)     // 30720 floats = 120 KB
#define WS_FLOATS (C_IN * 96)              // 12288 floats = 48 KB
#define SMEM_BYTES ((XS_FLOATS + WS_FLOATS) * 4)   // 172032 B

#define PS_STRIDE 17                        // u64 stride per thread (conflict pad)

typedef unsigned long long u64;

__device__ __forceinline__ u64 ffma2(u64 a, u64 b, u64 c) {
    u64 d;
    asm("fma.rn.f32x2 %0, %1, %2, %3;" : "=l"(d) : "l"(a), "l"(b), "l"(c));
    return d;
}
__device__ __forceinline__ u64 fadd2(u64 a, u64 b) {
    u64 d;
    asm("add.rn.f32x2 %0, %1, %2;" : "=l"(d) : "l"(a), "l"(b));
    return d;
}
__device__ __forceinline__ u64 pack2(float lo, float hi) {
    u64 d;
    asm("mov.b64 %0, {%1, %2};" : "=l"(d) : "f"(lo), "f"(hi));
    return d;
}
__device__ __forceinline__ void unpack2(float& lo, float& hi, u64 v) {
    asm("mov.b64 {%0, %1}, %2;" : "=f"(lo), "=f"(hi) : "l"(v));
}

__global__ __launch_bounds__(THREADS, 1)
void conv1x3_roll_kernel(const float* __restrict__ x,
                         const float* __restrict__ wgt,
                         float* __restrict__ out) {
    extern __shared__ float smem[];
    float* xs = smem;                    // [ROWS][C_IN][XPAD], xs[..][k] = x[w=k-1], halo zeros
    float* ws = smem + XS_FLOATS;        // [C_IN][3][32]: ws[c*96 + kw*32 + o]

    const int tid = threadIdx.x;
    const int n   = blockIdx.y;
    const int h0  = blockIdx.x * ROWS;

    // ---- load weights: wgt[o][c][kw] -> ws[c][kw][o] ----
    for (int i = tid; i < O_OUT * C_IN * 3; i += THREADS) {
        int o   = i / (C_IN * 3);
        int rem = i - o * (C_IN * 3);
        int c   = rem / 3;
        int kw  = rem - c * 3;
        ws[c * 96 + kw * 32 + o] = wgt[i];
    }

    // ---- load 4 x-rows (roll folded in) into padded smem ----
    #pragma unroll
    for (int r = 0; r < ROWS; ++r) {
        int h    = h0 + r;
        int hsrc = (h + H_IN - 1) % H_IN;          // roll(+1, axis=H)
        const float* xbase = x + ((size_t)(n * C_IN) * H_IN + hsrc) * W_IN;
        for (int i = tid; i < C_IN * (W_IN / 4); i += THREADS) {
            int c = i / 14;
            int v = i - c * 14;
            float4 val = *(const float4*)(xbase + (size_t)c * H_IN * W_IN + v * 4);
            float* dst = xs + (r * C_IN + c) * XPAD + 1 + v * 4;
            dst[0] = val.x; dst[1] = val.y; dst[2] = val.z; dst[3] = val.w;
        }
        for (int c = tid; c < C_IN; c += THREADS) {
            float* row = xs + (r * C_IN + c) * XPAD;
            row[0] = 0.0f; row[57] = 0.0f; row[58] = 0.0f; row[59] = 0.0f;
        }
    }
    __syncthreads();

    // ---- per-thread tile: 4 o x 8 w, packed over o-pairs; C split across 2 groups ----
    const int chalf = tid / GTHREADS;          // 0 or 1
    const int t0    = tid - chalf * GTHREADS;  // 0..223
    const int wt = t0 % WTILES;
    const int ot = (t0 / WTILES) % OTILES;
    const int r  = t0 / (WTILES * OTILES);
    const int w0 = wt * 8;
    const int o0 = ot * 4;

    u64 acc[2][8];
    #pragma unroll
    for (int p = 0; p < 2; ++p)
        #pragma unroll
        for (int j = 0; j < 8; ++j) acc[p][j] = 0ULL;

    const float* xp = xs + (size_t)r * C_IN * XPAD + w0;
    const u64*   wq = (const u64*)ws;
    const int cbeg = chalf * (C_IN / 2);

    #pragma unroll 4
    for (int ci = 0; ci < C_IN / 2; ++ci) {
        const int c = cbeg + ci;
        const float* xr = xp + c * XPAD;        // xr[j] = x[w = w0 + j - 1]
        float4 a = *(const float4*)(xr);
        float4 b = *(const float4*)(xr + 4);
        float2 e = *(const float2*)(xr + 8);

        u64 xb[10];
        xb[0] = pack2(a.x, a.x); xb[1] = pack2(a.y, a.y);
        xb[2] = pack2(a.z, a.z); xb[3] = pack2(a.w, a.w);
        xb[4] = pack2(b.x, b.x); xb[5] = pack2(b.y, b.y);
        xb[6] = pack2(b.z, b.z); xb[7] = pack2(b.w, b.w);
        xb[8] = pack2(e.x, e.x); xb[9] = pack2(e.y, e.y);

        const u64* wc = wq + c * 48 + ot * 2;   // c*96 floats = 48 pairs
        u64 wk[3][2];
        #pragma unroll
        for (int kw = 0; kw < 3; ++kw) {
            wk[kw][0] = wc[kw * 16];
            wk[kw][1] = wc[kw * 16 + 1];
        }

        #pragma unroll
        for (int kw = 0; kw < 3; ++kw) {
            #pragma unroll
            for (int j = 0; j < 8; ++j) {
                acc[0][j] = ffma2(wk[kw][0], xb[j + kw], acc[0][j]);
                acc[1][j] = ffma2(wk[kw][1], xb[j + kw], acc[1][j]);
            }
        }
    }

    // ---- cross-group reduction via smem (reuse xs region) ----
    __syncthreads();
    u64* ps = (u64*)smem;                      // 224 * 17 u64 = 30464 B < xs
    if (chalf == 1) {
        u64* dst = ps + (size_t)t0 * PS_STRIDE;
        #pragma unroll
        for (int p = 0; p < 2; ++p)
            #pragma unroll
            for (int j = 0; j < 8; ++j) dst[p * 8 + j] = acc[p][j];
    }
    __syncthreads();

    if (chalf == 0) {
        const u64* src = ps + (size_t)t0 * PS_STRIDE;
        #pragma unroll
        for (int p = 0; p < 2; ++p)
            #pragma unroll
            for (int j = 0; j < 8; ++j)
                acc[p][j] = fadd2(acc[p][j], src[p * 8 + j]);

        const int h = h0 + r;
        float res[4][8];
        #pragma unroll
        for (int p = 0; p < 2; ++p)
            #pragma unroll
            for (int j = 0; j < 8; ++j) {
                float lo, hi;
                unpack2(lo, hi, acc[p][j]);
                res[2 * p][j]     = lo;
                res[2 * p + 1][j] = hi;
            }

        #pragma unroll
        for (int oo = 0; oo < 4; ++oo) {
            float* op = out + (((size_t)n * O_OUT + (o0 + oo)) * H_IN + h) * W_IN + w0;
            *(float4*)(op)     = make_float4(res[oo][0], res[oo][1], res[oo][2], res[oo][3]);
            *(float4*)(op + 4) = make_float4(res[oo][4], res[oo][5], res[oo][6], res[oo][7]);
        }
    }
}

extern "C" void kernel_launch(void* const* d_in, const int* in_sizes, int n_in,
                              void* d_out, int out_size) {
    const float* x = (const float*)d_in[0];
    const float* w = (const float*)d_in[1];
    float* out = (float*)d_out;

    cudaFuncSetAttribute(conv1x3_roll_kernel,
                         cudaFuncAttributeMaxDynamicSharedMemorySize, SMEM_BYTES);

    dim3 grid(H_IN / ROWS, N_B);   // (14, 128)
    conv1x3_roll_kernel<<<grid, THREADS, SMEM_BYTES>>>(x, w, out);
}

// round 11
// speedup vs baseline: 1.1620x; 1.1607x over previous
#include <cuda_runtime.h>

#define W_IN    56
#define H_IN    56
#define C_IN    128
#define O_OUT   32
#define N_B     128
#define ROWS    4
#define XPAD    60
#define WTILES  7
#define OTILES  4                          // 8 o per thread
#define GTHREADS (ROWS * WTILES * OTILES)  // 112 per C-half
#define THREADS (2 * GTHREADS)             // 224 = 7 warps

#define XS_FLOATS (ROWS * C_IN * XPAD)     // 30720 floats = 120 KB
#define WS_FLOATS (C_IN * 96)              // 12288 floats = 48 KB
#define SMEM_BYTES ((XS_FLOATS + WS_FLOATS) * 4)   // 172032 B

#define PS_STRIDE 33                        // u64 stride per thread (conflict pad)

typedef unsigned long long u64;

__device__ __forceinline__ u64 ffma2(u64 a, u64 b, u64 c) {
    u64 d;
    asm("fma.rn.f32x2 %0, %1, %2, %3;" : "=l"(d) : "l"(a), "l"(b), "l"(c));
    return d;
}
__device__ __forceinline__ u64 fadd2(u64 a, u64 b) {
    u64 d;
    asm("add.rn.f32x2 %0, %1, %2;" : "=l"(d) : "l"(a), "l"(b));
    return d;
}
__device__ __forceinline__ u64 pack2(float lo, float hi) {
    u64 d;
    asm("mov.b64 %0, {%1, %2};" : "=l"(d) : "f"(lo), "f"(hi));
    return d;
}
__device__ __forceinline__ void unpack2(float& lo, float& hi, u64 v) {
    asm("mov.b64 {%0, %1}, %2;" : "=f"(lo), "=f"(hi) : "l"(v));
}

__global__ __launch_bounds__(THREADS, 1)
void conv1x3_roll_kernel(const float* __restrict__ x,
                         const float* __restrict__ wgt,
                         float* __restrict__ out) {
    extern __shared__ float smem[];
    float* xs = smem;                    // [ROWS][C_IN][XPAD], xs[..][k] = x[w=k-1], halo zeros
    float* ws = smem + XS_FLOATS;        // [C_IN][3][32]: ws[c*96 + kw*32 + o]

    const int tid = threadIdx.x;
    const int n   = blockIdx.y;
    const int h0  = blockIdx.x * ROWS;

    // ---- load weights: wgt[o][c][kw] -> ws[c][kw][o] ----
    for (int i = tid; i < O_OUT * C_IN * 3; i += THREADS) {
        int o   = i / (C_IN * 3);
        int rem = i - o * (C_IN * 3);
        int c   = rem / 3;
        int kw  = rem - c * 3;
        ws[c * 96 + kw * 32 + o] = wgt[i];
    }

    // ---- load 4 x-rows (roll folded in) into padded smem ----
    #pragma unroll
    for (int r = 0; r < ROWS; ++r) {
        int h    = h0 + r;
        int hsrc = (h + H_IN - 1) % H_IN;          // roll(+1, axis=H)
        const float* xbase = x + ((size_t)(n * C_IN) * H_IN + hsrc) * W_IN;
        for (int i = tid; i < C_IN * (W_IN / 4); i += THREADS) {
            int c = i / 14;
            int v = i - c * 14;
            float4 val = *(const float4*)(xbase + (size_t)c * H_IN * W_IN + v * 4);
            float* dst = xs + (r * C_IN + c) * XPAD + 1 + v * 4;
            dst[0] = val.x; dst[1] = val.y; dst[2] = val.z; dst[3] = val.w;
        }
        for (int c = tid; c < C_IN; c += THREADS) {
            float* row = xs + (r * C_IN + c) * XPAD;
            row[0] = 0.0f; row[57] = 0.0f; row[58] = 0.0f; row[59] = 0.0f;
        }
    }
    __syncthreads();

    // ---- per-thread tile: 8 o x 8 w (o-pair packed); C split across 2 groups ----
    const int chalf = tid / GTHREADS;          // 0 or 1
    const int t0    = tid - chalf * GTHREADS;  // 0..111
    const int wt = t0 % WTILES;
    const int ot = (t0 / WTILES) % OTILES;
    const int r  = t0 / (WTILES * OTILES);
    const int w0 = wt * 8;
    const int o0 = ot * 8;

    u64 acc[4][8];
    #pragma unroll
    for (int q = 0; q < 4; ++q)
        #pragma unroll
        for (int j = 0; j < 8; ++j) acc[q][j] = 0ULL;

    const float* xp = xs + (size_t)r * C_IN * XPAD + w0;
    const u64*   wq = (const u64*)ws;          // pair index = (c*96 + kw*32 + o)/2
    const int cbeg = chalf * (C_IN / 2);

    // ---- prologue: load c = cbeg operands ----
    const float* xr0 = xp + cbeg * XPAD;
    float4 xa = *(const float4*)(xr0);
    float4 xbv = *(const float4*)(xr0 + 4);
    float2 xe = *(const float2*)(xr0 + 8);
    u64 wk[3][4];
    {
        const u64* wc = wq + (size_t)cbeg * 48 + ot * 4;
        #pragma unroll
        for (int kw = 0; kw < 3; ++kw)
            #pragma unroll
            for (int q = 0; q < 4; ++q)
                wk[kw][q] = wc[kw * 16 + q];
    }

    #pragma unroll 2
    for (int ci = 0; ci < C_IN / 2; ++ci) {
        // ---- prefetch next c (clamped; last iter reloads same data, harmless) ----
        const int cin = cbeg + (ci < C_IN / 2 - 1 ? ci + 1 : ci);
        const float* xrn = xp + cin * XPAD;
        float4 na = *(const float4*)(xrn);
        float4 nb = *(const float4*)(xrn + 4);
        float2 ne = *(const float2*)(xrn + 8);
        u64 nwk[3][4];
        {
            const u64* wc = wq + (size_t)cin * 48 + ot * 4;
            #pragma unroll
            for (int kw = 0; kw < 3; ++kw)
                #pragma unroll
                for (int q = 0; q < 4; ++q)
                    nwk[kw][q] = wc[kw * 16 + q];
        }

        // ---- broadcast-pack current x ----
        u64 xb[10];
        xb[0] = pack2(xa.x, xa.x); xb[1] = pack2(xa.y, xa.y);
        xb[2] = pack2(xa.z, xa.z); xb[3] = pack2(xa.w, xa.w);
        xb[4] = pack2(xbv.x, xbv.x); xb[5] = pack2(xbv.y, xbv.y);
        xb[6] = pack2(xbv.z, xbv.z); xb[7] = pack2(xbv.w, xbv.w);
        xb[8] = pack2(xe.x, xe.x); xb[9] = pack2(xe.y, xe.y);

        // ---- 96 FFMA2 ----
        #pragma unroll
        for (int kw = 0; kw < 3; ++kw)
            #pragma unroll
            for (int j = 0; j < 8; ++j)
                #pragma unroll
                for (int q = 0; q < 4; ++q)
                    acc[q][j] = ffma2(wk[kw][q], xb[j + kw], acc[q][j]);

        // ---- rotate pipeline regs ----
        xa = na; xbv = nb; xe = ne;
        #pragma unroll
        for (int kw = 0; kw < 3; ++kw)
            #pragma unroll
            for (int q = 0; q < 4; ++q)
                wk[kw][q] = nwk[kw][q];
    }

    // ---- cross-group reduction via smem (reuse xs region) ----
    __syncthreads();
    u64* ps = (u64*)smem;                      // 112 * 33 u64 = 29568 B < xs
    if (chalf == 1) {
        u64* dst = ps + (size_t)t0 * PS_STRIDE;
        #pragma unroll
        for (int q = 0; q < 4; ++q)
            #pragma unroll
            for (int j = 0; j < 8; ++j) dst[q * 8 + j] = acc[q][j];
    }
    __syncthreads();

    if (chalf == 0) {
        const u64* src = ps + (size_t)t0 * PS_STRIDE;
        #pragma unroll
        for (int q = 0; q < 4; ++q)
            #pragma unroll
            for (int j = 0; j < 8; ++j)
                acc[q][j] = fadd2(acc[q][j], src[q * 8 + j]);

        const int h = h0 + r;
        float res[8][8];
        #pragma unroll
        for (int q = 0; q < 4; ++q)
            #pragma unroll
            for (int j = 0; j < 8; ++j) {
                float lo, hi;
                unpack2(lo, hi, acc[q][j]);
                res[2 * q][j]     = lo;
                res[2 * q + 1][j] = hi;
            }

        #pragma unroll
        for (int oo = 0; oo < 8; ++oo) {
            float* op = out + (((size_t)n * O_OUT + (o0 + oo)) * H_IN + h) * W_IN + w0;
            *(float4*)(op)     = make_float4(res[oo][0], res[oo][1], res[oo][2], res[oo][3]);
            *(float4*)(op + 4) = make_float4(res[oo][4], res[oo][5], res[oo][6], res[oo][7]);
        }
    }
}

extern "C" void kernel_launch(void* const* d_in, const int* in_sizes, int n_in,
                              void* d_out, int out_size) {
    const float* x = (const float*)d_in[0];
    const float* w = (const float*)d_in[1];
    float* out = (float*)d_out;

    cudaFuncSetAttribute(conv1x3_roll_kernel,
                         cudaFuncAttributeMaxDynamicSharedMemorySize, SMEM_BYTES);

    dim3 grid(H_IN / ROWS, N_B);   // (14, 128)
    conv1x3_roll_kernel<<<grid, THREADS, SMEM_BYTES>>>(x, w, out);
}